// round 15
// baseline (speedup 1.0000x reference)
#include <cuda_runtime.h>
#include <cuda_fp16.h>
#include <math.h>
#include <stdint.h>

// Problem constants
#define NB    2
#define TSEQ  2048
#define CDIM  2048
#define NH    16
#define NKV   4
#define HD    128
#define MROWS (NB * TSEQ)          // 4096
#define KVW   (2 * NKV * HD)       // 1024
#define KVHW  (NKV * HD)           // 512

// Scratch (no cudaMalloc allowed)
__device__ __half g_Qh[(size_t)MROWS * CDIM];
__device__ __half g_Kh[(size_t)MROWS * KVHW];
__device__ __half g_Vth[(size_t)NB * NKV * HD * TSEQ];
__device__ __half g_Yh[(size_t)MROWS * CDIM];
__device__ __half g_Xh[(size_t)MROWS * CDIM];
__device__ __half g_Wqh[(size_t)CDIM * CDIM];
__device__ __half g_Wkvh[(size_t)KVW * CDIM];
__device__ __half g_Woh[(size_t)CDIM * CDIM];

// ---------------------------------------------------------------------------
// Helpers
// ---------------------------------------------------------------------------
__device__ __forceinline__ void mma_f16(float* c,
                                        uint32_t a0, uint32_t a1, uint32_t a2, uint32_t a3,
                                        uint32_t b0, uint32_t b1) {
    asm("mma.sync.aligned.m16n8k16.row.col.f32.f16.f16.f32 "
        "{%0,%1,%2,%3}, {%4,%5,%6,%7}, {%8,%9}, {%0,%1,%2,%3};\n"
        : "+f"(c[0]), "+f"(c[1]), "+f"(c[2]), "+f"(c[3])
        : "r"(a0), "r"(a1), "r"(a2), "r"(a3), "r"(b0), "r"(b1));
}

__device__ __forceinline__ void cp_async16(uint32_t smem_addr, const void* gptr) {
    asm volatile("cp.async.cg.shared.global [%0], [%1], 16;\n"
                 :: "r"(smem_addr), "l"(gptr));
}

__device__ __forceinline__ void ldsm_x4(uint32_t& r0, uint32_t& r1, uint32_t& r2, uint32_t& r3,
                                        uint32_t addr) {
    asm volatile("ldmatrix.sync.aligned.m8n8.x4.shared.b16 {%0,%1,%2,%3}, [%4];"
                 : "=r"(r0), "=r"(r1), "=r"(r2), "=r"(r3) : "r"(addr));
}

// ---------------------------------------------------------------------------
// fp32 -> fp16 conversion for all four inputs in ONE launch
// ---------------------------------------------------------------------------
#define N4_X   (MROWS * CDIM / 4)
#define N4_WQ  (CDIM * CDIM / 4)
#define N4_WKV (KVW * CDIM / 4)
#define N4_WO  (CDIM * CDIM / 4)
#define N4_ALL (N4_X + N4_WQ + N4_WKV + N4_WO)

__global__ void cvt_all_kernel(const float* __restrict__ x, const float* __restrict__ wq,
                               const float* __restrict__ wkv, const float* __restrict__ wo,
                               __half* __restrict__ xh, __half* __restrict__ wqh,
                               __half* __restrict__ wkvh, __half* __restrict__ woh)
{
    int i = blockIdx.x * blockDim.x + threadIdx.x;
    const float* in;
    __half* out;
    int j = i;
    if (i < N4_X)                     { in = x;   out = xh;   }
    else if ((j -= N4_X)   < N4_WQ)   { in = wq;  out = wqh;  }
    else if ((j -= N4_WQ)  < N4_WKV)  { in = wkv; out = wkvh; }
    else if ((j -= N4_WKV) < N4_WO)   { in = wo;  out = woh;  }
    else return;
    float4 v = ((const float4*)in)[j];
    ((__half2*)out)[2 * j]     = __floats2half2_rn(v.x, v.y);
    ((__half2*)out)[2 * j + 1] = __floats2half2_rn(v.z, v.w);
}

// ---------------------------------------------------------------------------
// FP16 tensor-core NT GEMM with fused epilogues.
// 128x128 CTA tile, BK=32 halfs, 256 threads (8 warps 2x4), warp tile 64x32,
// 4-stage cp.async ring, ONE __syncthreads per iteration, ldmatrix frag loads.
// MODE 0: plain fp32 store to C (B = Bq).
// MODE 3: fused QKV: blockIdx.x < 16 -> Q proj (rope+scale -> O1=Qh);
//         else KV proj (B=Bkv): bn<512: K rope -> O2=Kh; else V^T -> O3=Vth.
// ---------------------------------------------------------------------------
#define BKH   32
#define PADH  40
#define TILEH (128 * PADH)            // halfs per A (or B) tile (5120)
#define NSTG  4
#define STGH  (2 * TILEH)             // halfs per stage (A+B)
#define GEMM_SMEM (NSTG * STGH * 2)   // 81920 bytes
#define PADE  130                     // fp32 epilogue tile stride (floats)

template <int MODE>
__global__ __launch_bounds__(256, 2) void gemm_f16_nt(
    const __half* __restrict__ A, const __half* __restrict__ Bq,
    const __half* __restrict__ Bkv,
    float* __restrict__ C, __half* __restrict__ O1, __half* __restrict__ O2,
    __half* __restrict__ O3, int M, int N, int K)
{
    extern __shared__ __half smh[];

    const int tid  = threadIdx.x;
    const int bm   = blockIdx.y * 128;
    const int warp = tid >> 5;
    const int lane = tid & 31;
    const int wm   = warp >> 2;        // 0..1
    const int wn   = warp & 3;         // 0..3
    const int gid  = lane >> 2;        // 0..7
    const int tig  = lane & 3;         // 0..3

    // B selection (MODE 3: Q tiles then KV tiles)
    const bool isQ = (MODE != 3) || (blockIdx.x < CDIM / 128);
    const __half* Bsel = (MODE == 3 && !isQ) ? Bkv : Bq;
    const int bn = (MODE == 3 && !isQ) ? (blockIdx.x - CDIM / 128) * 128
                                       : blockIdx.x * 128;

    const int crow = tid >> 1;
    const int cq   = tid & 1;
    const __half* gA = A + (size_t)(bm + crow) * K + cq * 16;
    const __half* gB = Bsel + (size_t)(bn + crow) * K + cq * 16;
    const int soff = crow * PADH + cq * 16;

    // ldmatrix per-lane row addresses (byte offsets within a stage).
    // A x4 for (mt): matrices [r0,kc],[r0+8,kc],[r0,kc+8],[r0+8,kc+8]
    //   lane l: m = l>>3, j = l&7 -> row = wm*64+mt*16+(m&1)*8+j, col = (m>>1)*8
    // B x4 for pair p (nt=2p,2p+1): [n0,kc],[n0,kc+8],[n0+16? no: n0+8? ...]
    //   matrices [wn*32+p*16+(m>>1)*8+j, (m&1)*8] -> regs bf[2p][0],bf[2p][1],bf[2p+1][0],bf[2p+1][1]
    uint32_t a_off[4], b_off[2];
    {
        const int m = lane >> 3, j = lane & 7;
#pragma unroll
        for (int mt = 0; mt < 4; mt++)
            a_off[mt] = ((wm * 64 + mt * 16 + (m & 1) * 8 + j) * PADH + (m >> 1) * 8) * 2;
#pragma unroll
        for (int p = 0; p < 2; p++)
            b_off[p] = ((wn * 32 + p * 16 + (m >> 1) * 8 + j) * PADH + (m & 1) * 8) * 2;
    }
    const uint32_t smBase = (uint32_t)__cvta_generic_to_shared(smh);

    float acc[4][4][4];
#pragma unroll
    for (int mt = 0; mt < 4; mt++)
#pragma unroll
        for (int nt = 0; nt < 4; nt++)
#pragma unroll
            for (int i = 0; i < 4; i++) acc[mt][nt][i] = 0.f;

    const int niter = K / BKH;

    // prologue: stages 0..NSTG-2
#pragma unroll
    for (int p = 0; p < NSTG - 1; p++) {
        const int koff = p * BKH;
        uint32_t sa = smBase + (p * STGH + soff) * 2;
        uint32_t sb = sa + TILEH * 2;
#pragma unroll
        for (int j = 0; j < 2; j++) {
            cp_async16(sa + j * 16, gA + koff + j * 8);
            cp_async16(sb + j * 16, gB + koff + j * 8);
        }
        asm volatile("cp.async.commit_group;\n" ::: "memory");
    }

    for (int k0 = 0; k0 < niter; k0++) {
        const int buf = k0 & (NSTG - 1);
        asm volatile("cp.async.wait_group %0;\n" :: "n"(NSTG - 2) : "memory");
        __syncthreads();   // (a) stage k0 visible; (b) buffer (k0-1)%NSTG free

        if (k0 + NSTG - 1 < niter) {
            const int koff = (k0 + NSTG - 1) * BKH;
            uint32_t sa = smBase + (((k0 + NSTG - 1) & (NSTG - 1)) * STGH + soff) * 2;
            uint32_t sb = sa + TILEH * 2;
#pragma unroll
            for (int j = 0; j < 2; j++) {
                cp_async16(sa + j * 16, gA + koff + j * 8);
                cp_async16(sb + j * 16, gB + koff + j * 8);
            }
        }
        asm volatile("cp.async.commit_group;\n" ::: "memory");

        const uint32_t aBase = smBase + buf * STGH * 2;
        const uint32_t bBase = aBase + TILEH * 2;
#pragma unroll
        for (int ks = 0; ks < 2; ks++) {
            const uint32_t kb = ks * 32;   // 16 halfs = 32 bytes
            uint32_t af[4][4], bf[4][2];
#pragma unroll
            for (int mt = 0; mt < 4; mt++)
                ldsm_x4(af[mt][0], af[mt][1], af[mt][2], af[mt][3], aBase + a_off[mt] + kb);
#pragma unroll
            for (int p = 0; p < 2; p++)
                ldsm_x4(bf[2*p][0], bf[2*p][1], bf[2*p+1][0], bf[2*p+1][1],
                        bBase + b_off[p] + kb);
#pragma unroll
            for (int mt = 0; mt < 4; mt++)
#pragma unroll
                for (int nt = 0; nt < 4; nt++)
                    mma_f16(acc[mt][nt], af[mt][0], af[mt][1], af[mt][2], af[mt][3],
                            bf[nt][0], bf[nt][1]);
        }
    }

    if (MODE == 0) {
#pragma unroll
        for (int mt = 0; mt < 4; mt++) {
            const int r0 = bm + wm * 64 + mt * 16 + gid;
#pragma unroll
            for (int nt = 0; nt < 4; nt++) {
                const int c0 = bn + wn * 32 + nt * 8 + tig * 2;
                *(float2*)&C[(size_t)r0 * N + c0]       = make_float2(acc[mt][nt][0], acc[mt][nt][1]);
                *(float2*)&C[(size_t)(r0 + 8) * N + c0] = make_float2(acc[mt][nt][2], acc[mt][nt][3]);
            }
        }
        return;
    }

    // ---- fused epilogue via smem fp32 tile [128][PADE] ----
    float* S = (float*)smh;
    __syncthreads();   // all pipeline reads done before smem reuse
#pragma unroll
    for (int mt = 0; mt < 4; mt++) {
        const int r = wm * 64 + mt * 16 + gid;
#pragma unroll
        for (int nt = 0; nt < 4; nt++) {
            const int c = wn * 32 + nt * 8 + tig * 2;
            *(float2*)&S[r * PADE + c]       = make_float2(acc[mt][nt][0], acc[mt][nt][1]);
            *(float2*)&S[(r + 8) * PADE + c] = make_float2(acc[mt][nt][2], acc[mt][nt][3]);
        }
    }
    __syncthreads();

    if (isQ || bn < KVHW) {
        const int head = bn >> 7;
        const float scale = isQ ? 0.08838834764831845f : 1.0f;
        __half* O = isQ ? O1 : O2;
        const int rowW = isQ ? CDIM : KVHW;
#pragma unroll
        for (int j = 0; j < 32; j++) {
            int p = tid + j * 256;          // 0..8191
            int r = p >> 6, i = p & 63;
            int row = bm + r;
            int t = row & (TSEQ - 1);
            float freq = expf(-(float)i * (9.210340371976184f / 64.0f));
            float sn, cs;
            sincosf((float)t * freq, &sn, &cs);
            float x0 = S[r * PADE + i];
            float x1 = S[r * PADE + i + 64];
            __half* o = O + (size_t)row * rowW + head * 128;
            o[i]      = __float2half((x0 * cs - x1 * sn) * scale);
            o[i + 64] = __float2half((x1 * cs + x0 * sn) * scale);
        }
    } else {
        const int kv = (bn - KVHW) >> 7;
        const int b  = bm >> 11;
        const int tbase = bm & (TSEQ - 1);
        __half* Obase = O3 + ((size_t)(b * NKV + kv) * HD) * TSEQ + tbase;
#pragma unroll
        for (int j = 0; j < 64; j++) {
            int e = tid + j * 256;          // 0..16383
            int d = e >> 7, r = e & 127;
            Obase[(size_t)d * TSEQ + r] = __float2half(S[r * PADE + d]);
        }
    }
}

// ---------------------------------------------------------------------------
// FP16 tensor-core causal flash attention (fp32 softmax/accum).
// Heaviest-first scheduling.
// ---------------------------------------------------------------------------
#define KPADH 136
#define VPADH 40
#define PPADH 40
#define KTILEH (32 * KPADH)
#define VTILEH (128 * VPADH)
#define BUFH   (KTILEH + VTILEH)
#define ATTN_SMEM ((2 * BUFH + 64 * PPADH) * 2)   // 43008 bytes

__global__ __launch_bounds__(128, 2) void attn_f16_kernel(
    const __half* __restrict__ Qh, const __half* __restrict__ Kh,
    const __half* __restrict__ Vt, __half* __restrict__ Y)
{
    extern __shared__ __half smh[];
    __half* Ps = smh + 2 * BUFH;

    const int b   = blockIdx.z;
    const int h   = blockIdx.y;
    const int q0  = (int)(gridDim.x - 1 - blockIdx.x) * 64;   // heaviest first
    const int kvh = h >> 2;
    const int tid  = threadIdx.x;
    const int warp = tid >> 5;
    const int lane = tid & 31;
    const int gid  = lane >> 2;
    const int tig  = lane & 3;

    uint32_t qf[8][4];
    {
        const __half* qp  = Qh + (size_t)(b * TSEQ + q0 + warp * 16 + gid) * CDIM + h * 128;
        const __half* qp8 = qp + 8 * CDIM;
#pragma unroll
        for (int ks = 0; ks < 8; ks++) {
            qf[ks][0] = *(const uint32_t*)&qp [ks * 16 + 2 * tig];
            qf[ks][1] = *(const uint32_t*)&qp8[ks * 16 + 2 * tig];
            qf[ks][2] = *(const uint32_t*)&qp [ks * 16 + 8 + 2 * tig];
            qf[ks][3] = *(const uint32_t*)&qp8[ks * 16 + 8 + 2 * tig];
        }
    }

    float o[16][4];
#pragma unroll
    for (int nt = 0; nt < 16; nt++)
#pragma unroll
        for (int i = 0; i < 4; i++) o[nt][i] = 0.f;
    float m0 = -1e30f, m1 = -1e30f, l0 = 0.f, l1 = 0.f;

    const int nkt = q0 / 32 + 2;

    const __half* Kbase  = Kh + (size_t)(b * TSEQ) * KVHW + kvh * 128;
    const __half* Vtbase = Vt + ((size_t)(b * NKV + kvh) * HD) * TSEQ;

    {
        __half* Kb = smh;
        __half* Vb = smh + KTILEH;
#pragma unroll
        for (int i = 0; i < 4; i++) {
            int idx = tid + i * 128;
            int kr = idx >> 4, kc = idx & 15;
            cp_async16((uint32_t)__cvta_generic_to_shared(Kb + kr * KPADH + kc * 8),
                       Kbase + (size_t)kr * KVHW + kc * 8);
            int vr = idx >> 2, vc = idx & 3;
            cp_async16((uint32_t)__cvta_generic_to_shared(Vb + vr * VPADH + vc * 8),
                       Vtbase + (size_t)vr * TSEQ + vc * 8);
        }
        asm volatile("cp.async.commit_group;\n" ::: "memory");
    }

    const int row0 = warp * 16 + gid;

    for (int t = 0; t < nkt; t++) {
        const int buf = t & 1;
        if (t + 1 < nkt) {
            const int s1 = (t + 1) * 32;
            __half* Kb = smh + (buf ^ 1) * BUFH;
            __half* Vb = Kb + KTILEH;
#pragma unroll
            for (int i = 0; i < 4; i++) {
                int idx = tid + i * 128;
                int kr = idx >> 4, kc = idx & 15;
                cp_async16((uint32_t)__cvta_generic_to_shared(Kb + kr * KPADH + kc * 8),
                           Kbase + (size_t)(s1 + kr) * KVHW + kc * 8);
                int vr = idx >> 2, vc = idx & 3;
                cp_async16((uint32_t)__cvta_generic_to_shared(Vb + vr * VPADH + vc * 8),
                           Vtbase + (size_t)vr * TSEQ + s1 + vc * 8);
            }
        }
        asm volatile("cp.async.commit_group;\n" ::: "memory");
        asm volatile("cp.async.wait_group 1;\n" ::: "memory");
        __syncthreads();

        const __half* Kb = smh + buf * BUFH;
        const __half* Vb = Kb + KTILEH;
        const int s0 = t * 32;

        float s[4][4];
#pragma unroll
        for (int nt = 0; nt < 4; nt++)
#pragma unroll
            for (int i = 0; i < 4; i++) s[nt][i] = 0.f;

#pragma unroll
        for (int ks = 0; ks < 8; ks++) {
            const int kc = ks * 16;
#pragma unroll
            for (int nt = 0; nt < 4; nt++) {
                const __half* kr = Kb + (nt * 8 + gid) * KPADH + kc + 2 * tig;
                uint32_t b0 = *(const uint32_t*)kr;
                uint32_t b1 = *(const uint32_t*)(kr + 8);
                mma_f16(s[nt], qf[ks][0], qf[ks][1], qf[ks][2], qf[ks][3], b0, b1);
            }
        }

        if (t >= nkt - 2) {
            const int r0g = q0 + row0;
#pragma unroll
            for (int nt = 0; nt < 4; nt++) {
                const int c = s0 + nt * 8 + tig * 2;
                if (c > r0g)         s[nt][0] = -1e30f;
                if (c + 1 > r0g)     s[nt][1] = -1e30f;
                if (c > r0g + 8)     s[nt][2] = -1e30f;
                if (c + 1 > r0g + 8) s[nt][3] = -1e30f;
            }
        }

        float rm0 = s[0][0], rm1 = s[0][2];
#pragma unroll
        for (int nt = 0; nt < 4; nt++) {
            rm0 = fmaxf(rm0, fmaxf(s[nt][0], s[nt][1]));
            rm1 = fmaxf(rm1, fmaxf(s[nt][2], s[nt][3]));
        }
        rm0 = fmaxf(rm0, __shfl_xor_sync(0xffffffffu, rm0, 1));
        rm0 = fmaxf(rm0, __shfl_xor_sync(0xffffffffu, rm0, 2));
        rm1 = fmaxf(rm1, __shfl_xor_sync(0xffffffffu, rm1, 1));
        rm1 = fmaxf(rm1, __shfl_xor_sync(0xffffffffu, rm1, 2));

        float mt0 = fmaxf(m0, rm0), mt1 = fmaxf(m1, rm1);
        float c0 = __expf(m0 - mt0), c1 = __expf(m1 - mt1);
        m0 = mt0; m1 = mt1;

        float rs0 = 0.f, rs1 = 0.f;
#pragma unroll
        for (int nt = 0; nt < 4; nt++) {
            s[nt][0] = __expf(s[nt][0] - m0); rs0 += s[nt][0];
            s[nt][1] = __expf(s[nt][1] - m0); rs0 += s[nt][1];
            s[nt][2] = __expf(s[nt][2] - m1); rs1 += s[nt][2];
            s[nt][3] = __expf(s[nt][3] - m1); rs1 += s[nt][3];
        }
        rs0 += __shfl_xor_sync(0xffffffffu, rs0, 1);
        rs0 += __shfl_xor_sync(0xffffffffu, rs0, 2);
        rs1 += __shfl_xor_sync(0xffffffffu, rs1, 1);
        rs1 += __shfl_xor_sync(0xffffffffu, rs1, 2);
        l0 = l0 * c0 + rs0;
        l1 = l1 * c1 + rs1;

#pragma unroll
        for (int nt = 0; nt < 16; nt++) {
            o[nt][0] *= c0; o[nt][1] *= c0;
            o[nt][2] *= c1; o[nt][3] *= c1;
        }

#pragma unroll
        for (int nt = 0; nt < 4; nt++) {
            *(__half2*)&Ps[row0 * PPADH + nt * 8 + 2 * tig]       = __floats2half2_rn(s[nt][0], s[nt][1]);
            *(__half2*)&Ps[(row0 + 8) * PPADH + nt * 8 + 2 * tig] = __floats2half2_rn(s[nt][2], s[nt][3]);
        }
        __syncwarp();

#pragma unroll
        for (int ks = 0; ks < 2; ks++) {
            const int kc = ks * 16;
            uint32_t a0 = *(const uint32_t*)&Ps[row0 * PPADH + kc + 2 * tig];
            uint32_t a1 = *(const uint32_t*)&Ps[(row0 + 8) * PPADH + kc + 2 * tig];
            uint32_t a2 = *(const uint32_t*)&Ps[row0 * PPADH + kc + 8 + 2 * tig];
            uint32_t a3 = *(const uint32_t*)&Ps[(row0 + 8) * PPADH + kc + 8 + 2 * tig];
#pragma unroll
            for (int nt = 0; nt < 16; nt++) {
                const __half* vr = Vb + (nt * 8 + gid) * VPADH + kc + 2 * tig;
                uint32_t b0 = *(const uint32_t*)vr;
                uint32_t b1 = *(const uint32_t*)(vr + 8);
                mma_f16(o[nt], a0, a1, a2, a3, b0, b1);
            }
        }
        __syncthreads();
    }

    const float inv0 = 1.f / l0, inv1 = 1.f / l1;
    __half* yp  = Y + (size_t)(b * TSEQ + q0 + row0) * CDIM + h * 128;
    __half* yp8 = yp + 8 * CDIM;
#pragma unroll
    for (int nt = 0; nt < 16; nt++) {
        const int c = nt * 8 + tig * 2;
        *(__half2*)&yp [c] = __floats2half2_rn(o[nt][0] * inv0, o[nt][1] * inv0);
        *(__half2*)&yp8[c] = __floats2half2_rn(o[nt][2] * inv1, o[nt][3] * inv1);
    }
}

// ---------------------------------------------------------------------------
extern "C" void kernel_launch(void* const* d_in, const int* in_sizes, int n_in,
                              void* d_out, int out_size)
{
    const float* x   = (const float*)d_in[0];
    const float* Wq  = (const float*)d_in[1];
    const float* Wkv = (const float*)d_in[2];
    const float* Wo  = (const float*)d_in[3];
    float* out = (float*)d_out;

    __half *pQh, *pKh, *pVth, *pYh, *pXh, *pWqh, *pWkvh, *pWoh;
    cudaGetSymbolAddress((void**)&pQh,   g_Qh);
    cudaGetSymbolAddress((void**)&pKh,   g_Kh);
    cudaGetSymbolAddress((void**)&pVth,  g_Vth);
    cudaGetSymbolAddress((void**)&pYh,   g_Yh);
    cudaGetSymbolAddress((void**)&pXh,   g_Xh);
    cudaGetSymbolAddress((void**)&pWqh,  g_Wqh);
    cudaGetSymbolAddress((void**)&pWkvh, g_Wkvh);
    cudaGetSymbolAddress((void**)&pWoh,  g_Woh);

    cudaFuncSetAttribute(gemm_f16_nt<0>, cudaFuncAttributeMaxDynamicSharedMemorySize, GEMM_SMEM);
    cudaFuncSetAttribute(gemm_f16_nt<3>, cudaFuncAttributeMaxDynamicSharedMemorySize, GEMM_SMEM);
    cudaFuncSetAttribute(attn_f16_kernel, cudaFuncAttributeMaxDynamicSharedMemorySize, ATTN_SMEM);

    // 0) convert all four inputs to fp16 in one launch
    cvt_all_kernel<<<(N4_ALL + 255) / 256, 256>>>(x, Wq, Wkv, Wo, pXh, pWqh, pWkvh, pWoh);

    // 1) fused QKV projection (Q: rope+scale -> Qh; K: rope -> Kh; V: ^T -> Vth)
    gemm_f16_nt<3><<<dim3((CDIM + KVW) / 128, MROWS / 128), 256, GEMM_SMEM>>>(
        pXh, pWqh, pWkvh, nullptr, pQh, pKh, pVth, MROWS, 0, CDIM);

    // 2) fp16 tensor-core causal flash attention (fp16 Y out)
    attn_f16_kernel<<<dim3(TSEQ / 64, NH, NB), 128, ATTN_SMEM>>>(pQh, pKh, pVth, pYh);

    // 3) out = Y @ Wo^T (fp16 in, fp32 out)
    gemm_f16_nt<0><<<dim3(CDIM / 128, MROWS / 128), 256, GEMM_SMEM>>>(
        pYh, pWoh, nullptr, out, nullptr, nullptr, nullptr, MROWS, CDIM, CDIM);
}

// round 16
// speedup vs baseline: 1.5470x; 1.5470x over previous
#include <cuda_runtime.h>
#include <cuda_fp16.h>
#include <math.h>
#include <stdint.h>

// Problem constants
#define NB    2
#define TSEQ  2048
#define CDIM  2048
#define NH    16
#define NKV   4
#define HD    128
#define MROWS (NB * TSEQ)          // 4096
#define KVW   (2 * NKV * HD)       // 1024
#define KVHW  (NKV * HD)           // 512

// Scratch (no cudaMalloc allowed)
__device__ __half g_Qh[(size_t)MROWS * CDIM];
__device__ __half g_Kh[(size_t)MROWS * KVHW];
__device__ __half g_Vth[(size_t)NB * NKV * HD * TSEQ];
__device__ __half g_Yh[(size_t)MROWS * CDIM];
__device__ __half g_Xh[(size_t)MROWS * CDIM];
__device__ __half g_Wqh[(size_t)CDIM * CDIM];
__device__ __half g_Wkvh[(size_t)KVW * CDIM];
__device__ __half g_Woh[(size_t)CDIM * CDIM];

// ---------------------------------------------------------------------------
// Helpers
// ---------------------------------------------------------------------------
__device__ __forceinline__ void mma_f16(float* c,
                                        uint32_t a0, uint32_t a1, uint32_t a2, uint32_t a3,
                                        uint32_t b0, uint32_t b1) {
    asm("mma.sync.aligned.m16n8k16.row.col.f32.f16.f16.f32 "
        "{%0,%1,%2,%3}, {%4,%5,%6,%7}, {%8,%9}, {%0,%1,%2,%3};\n"
        : "+f"(c[0]), "+f"(c[1]), "+f"(c[2]), "+f"(c[3])
        : "r"(a0), "r"(a1), "r"(a2), "r"(a3), "r"(b0), "r"(b1));
}

__device__ __forceinline__ void cp_async16(uint32_t smem_addr, const void* gptr) {
    asm volatile("cp.async.cg.shared.global [%0], [%1], 16;\n"
                 :: "r"(smem_addr), "l"(gptr));
}

// ---------------------------------------------------------------------------
// fp32 -> fp16 conversion for all four inputs in ONE launch
// ---------------------------------------------------------------------------
#define N4_X   (MROWS * CDIM / 4)
#define N4_WQ  (CDIM * CDIM / 4)
#define N4_WKV (KVW * CDIM / 4)
#define N4_WO  (CDIM * CDIM / 4)
#define N4_ALL (N4_X + N4_WQ + N4_WKV + N4_WO)

__global__ void cvt_all_kernel(const float* __restrict__ x, const float* __restrict__ wq,
                               const float* __restrict__ wkv, const float* __restrict__ wo,
                               __half* __restrict__ xh, __half* __restrict__ wqh,
                               __half* __restrict__ wkvh, __half* __restrict__ woh)
{
    int i = blockIdx.x * blockDim.x + threadIdx.x;
    const float* in;
    __half* out;
    int j = i;
    if (i < N4_X)                     { in = x;   out = xh;   }
    else if ((j -= N4_X)   < N4_WQ)   { in = wq;  out = wqh;  }
    else if ((j -= N4_WQ)  < N4_WKV)  { in = wkv; out = wkvh; }
    else if ((j -= N4_WKV) < N4_WO)   { in = wo;  out = woh;  }
    else return;
    float4 v = ((const float4*)in)[j];
    ((__half2*)out)[2 * j]     = __floats2half2_rn(v.x, v.y);
    ((__half2*)out)[2 * j + 1] = __floats2half2_rn(v.z, v.w);
}

// ---------------------------------------------------------------------------
// FP16 tensor-core NT GEMM, fused QKV epilogues (R13-exact).
// 128x128 CTA tile, BK=32 halfs, 256 threads (8 warps 2x4), warp tile 64x32,
// 4-stage cp.async ring, ONE __syncthreads per iteration, scalar LDS frags.
// blockIdx.x < 16 -> Q proj (rope+scale -> O1=Qh);
// else KV proj (B=Bkv): bn<512: K rope -> O2=Kh; else V^T -> O3=Vth.
// ---------------------------------------------------------------------------
#define BKH   32
#define PADH  40
#define TILEH (128 * PADH)            // halfs per A (or B) tile (5120)
#define NSTG  4
#define STGH  (2 * TILEH)             // halfs per stage (A+B)
#define GEMM_SMEM (NSTG * STGH * 2)   // 81920 bytes
#define PADE  130                     // fp32 epilogue tile stride (floats)

__global__ __launch_bounds__(256, 2) void gemm_qkv(
    const __half* __restrict__ A, const __half* __restrict__ Bq,
    const __half* __restrict__ Bkv,
    __half* __restrict__ O1, __half* __restrict__ O2, __half* __restrict__ O3,
    int K)
{
    extern __shared__ __half smh[];

    const int tid  = threadIdx.x;
    const int bm   = blockIdx.y * 128;
    const int warp = tid >> 5;
    const int lane = tid & 31;
    const int wm   = warp >> 2;
    const int wn   = warp & 3;
    const int gid  = lane >> 2;
    const int tig  = lane & 3;

    const bool isQ = (blockIdx.x < CDIM / 128);
    const __half* Bsel = isQ ? Bq : Bkv;
    const int bn = isQ ? blockIdx.x * 128 : (blockIdx.x - CDIM / 128) * 128;

    const int crow = tid >> 1;
    const int cq   = tid & 1;
    const __half* gA = A + (size_t)(bm + crow) * K + cq * 16;
    const __half* gB = Bsel + (size_t)(bn + crow) * K + cq * 16;
    const int soff = crow * PADH + cq * 16;

    float acc[4][4][4];
#pragma unroll
    for (int mt = 0; mt < 4; mt++)
#pragma unroll
        for (int nt = 0; nt < 4; nt++)
#pragma unroll
            for (int i = 0; i < 4; i++) acc[mt][nt][i] = 0.f;

    const int niter = K / BKH;

#pragma unroll
    for (int p = 0; p < NSTG - 1; p++) {
        const int koff = p * BKH;
        uint32_t sa = (uint32_t)__cvta_generic_to_shared(smh + p * STGH + soff);
        uint32_t sb = sa + TILEH * 2;
#pragma unroll
        for (int j = 0; j < 2; j++) {
            cp_async16(sa + j * 16, gA + koff + j * 8);
            cp_async16(sb + j * 16, gB + koff + j * 8);
        }
        asm volatile("cp.async.commit_group;\n" ::: "memory");
    }

    for (int k0 = 0; k0 < niter; k0++) {
        const int buf = k0 & (NSTG - 1);
        asm volatile("cp.async.wait_group %0;\n" :: "n"(NSTG - 2) : "memory");
        __syncthreads();

        if (k0 + NSTG - 1 < niter) {
            const int koff = (k0 + NSTG - 1) * BKH;
            uint32_t sa = (uint32_t)__cvta_generic_to_shared(
                smh + ((k0 + NSTG - 1) & (NSTG - 1)) * STGH + soff);
            uint32_t sb = sa + TILEH * 2;
#pragma unroll
            for (int j = 0; j < 2; j++) {
                cp_async16(sa + j * 16, gA + koff + j * 8);
                cp_async16(sb + j * 16, gB + koff + j * 8);
            }
        }
        asm volatile("cp.async.commit_group;\n" ::: "memory");

        const __half* As = smh + buf * STGH;
        const __half* Bs = As + TILEH;
#pragma unroll
        for (int ks = 0; ks < 2; ks++) {
            const int kc = ks * 16;
            uint32_t af[4][4], bf[4][2];
#pragma unroll
            for (int mt = 0; mt < 4; mt++) {
                const int r = wm * 64 + mt * 16 + gid;
                af[mt][0] = *(const uint32_t*)&As[r * PADH + kc + 2 * tig];
                af[mt][1] = *(const uint32_t*)&As[(r + 8) * PADH + kc + 2 * tig];
                af[mt][2] = *(const uint32_t*)&As[r * PADH + kc + 8 + 2 * tig];
                af[mt][3] = *(const uint32_t*)&As[(r + 8) * PADH + kc + 8 + 2 * tig];
            }
#pragma unroll
            for (int nt = 0; nt < 4; nt++) {
                const int r = wn * 32 + nt * 8 + gid;
                bf[nt][0] = *(const uint32_t*)&Bs[r * PADH + kc + 2 * tig];
                bf[nt][1] = *(const uint32_t*)&Bs[r * PADH + kc + 8 + 2 * tig];
            }
#pragma unroll
            for (int mt = 0; mt < 4; mt++)
#pragma unroll
                for (int nt = 0; nt < 4; nt++)
                    mma_f16(acc[mt][nt], af[mt][0], af[mt][1], af[mt][2], af[mt][3],
                            bf[nt][0], bf[nt][1]);
        }
    }

    // ---- fused epilogue via smem fp32 tile [128][PADE] ----
    float* S = (float*)smh;
    __syncthreads();
#pragma unroll
    for (int mt = 0; mt < 4; mt++) {
        const int r = wm * 64 + mt * 16 + gid;
#pragma unroll
        for (int nt = 0; nt < 4; nt++) {
            const int c = wn * 32 + nt * 8 + tig * 2;
            *(float2*)&S[r * PADE + c]       = make_float2(acc[mt][nt][0], acc[mt][nt][1]);
            *(float2*)&S[(r + 8) * PADE + c] = make_float2(acc[mt][nt][2], acc[mt][nt][3]);
        }
    }
    __syncthreads();

    if (isQ || bn < KVHW) {
        const int head = bn >> 7;
        const float scale = isQ ? 0.08838834764831845f : 1.0f;
        __half* O = isQ ? O1 : O2;
        const int rowW = isQ ? CDIM : KVHW;
#pragma unroll
        for (int j = 0; j < 32; j++) {
            int p = tid + j * 256;
            int r = p >> 6, i = p & 63;
            int row = bm + r;
            int t = row & (TSEQ - 1);
            float freq = expf(-(float)i * (9.210340371976184f / 64.0f));
            float sn, cs;
            sincosf((float)t * freq, &sn, &cs);
            float x0 = S[r * PADE + i];
            float x1 = S[r * PADE + i + 64];
            __half* o = O + (size_t)row * rowW + head * 128;
            o[i]      = __float2half((x0 * cs - x1 * sn) * scale);
            o[i + 64] = __float2half((x1 * cs + x0 * sn) * scale);
        }
    } else {
        const int kv = (bn - KVHW) >> 7;
        const int b  = bm >> 11;
        const int tbase = bm & (TSEQ - 1);
        __half* Obase = O3 + ((size_t)(b * NKV + kv) * HD) * TSEQ + tbase;
#pragma unroll
        for (int j = 0; j < 64; j++) {
            int e = tid + j * 256;
            int d = e >> 7, r = e & 127;
            Obase[(size_t)d * TSEQ + r] = __float2half(S[r * PADE + d]);
        }
    }
}

// ---------------------------------------------------------------------------
// FP16 NT GEMM, 128x64 CTA tile for the O-projection (plain fp32 store).
// 256 threads (8 warps 4x2), warp tile 32x32, 4-stage ring, single barrier.
// ~80 regs -> 3 CTAs/SM (24 warps) for better latency hiding.
// ---------------------------------------------------------------------------
#define STGH64 (192 * PADH)             // A(128) + B(64) rows per stage (7680 halfs)
#define GEMM64_SMEM (NSTG * STGH64 * 2) // 61440 bytes

__global__ __launch_bounds__(256, 3) void gemm_wo64(
    const __half* __restrict__ A, const __half* __restrict__ B,
    float* __restrict__ C, int N, int K)
{
    extern __shared__ __half smh[];

    const int tid  = threadIdx.x;
    const int bm   = blockIdx.y * 128;
    const int bn   = blockIdx.x * 64;
    const int warp = tid >> 5;
    const int lane = tid & 31;
    const int wm   = warp >> 1;        // 0..3 (32-row slab)
    const int wn   = warp & 1;         // 0..1 (32-col slab)
    const int gid  = lane >> 2;
    const int tig  = lane & 3;

    // loaders: A 128 rows x 2x16B per row (all 256 thr); B 64 rows x 1x16B (tid<256: tid>>2 row, tid&3 chunk)
    const int arow = tid >> 1, aq = tid & 1;
    const __half* gA = A + (size_t)(bm + arow) * K + aq * 16;
    const int aoff = arow * PADH + aq * 16;
    const int brow = tid >> 2, bq = tid & 3;
    const __half* gB = B + (size_t)(bn + brow) * K + bq * 8;
    const int boff = 128 * PADH + brow * PADH + bq * 8;

    float acc[2][4][4];
#pragma unroll
    for (int mt = 0; mt < 2; mt++)
#pragma unroll
        for (int nt = 0; nt < 4; nt++)
#pragma unroll
            for (int i = 0; i < 4; i++) acc[mt][nt][i] = 0.f;

    const int niter = K / BKH;

#pragma unroll
    for (int p = 0; p < NSTG - 1; p++) {
        const int koff = p * BKH;
        uint32_t sa = (uint32_t)__cvta_generic_to_shared(smh + p * STGH64 + aoff);
        uint32_t sb = (uint32_t)__cvta_generic_to_shared(smh + p * STGH64 + boff);
        cp_async16(sa,      gA + koff);
        cp_async16(sa + 16, gA + koff + 8);
        cp_async16(sb,      gB + koff);
        asm volatile("cp.async.commit_group;\n" ::: "memory");
    }

    for (int k0 = 0; k0 < niter; k0++) {
        const int buf = k0 & (NSTG - 1);
        asm volatile("cp.async.wait_group %0;\n" :: "n"(NSTG - 2) : "memory");
        __syncthreads();

        if (k0 + NSTG - 1 < niter) {
            const int koff = (k0 + NSTG - 1) * BKH;
            const int st = (k0 + NSTG - 1) & (NSTG - 1);
            uint32_t sa = (uint32_t)__cvta_generic_to_shared(smh + st * STGH64 + aoff);
            uint32_t sb = (uint32_t)__cvta_generic_to_shared(smh + st * STGH64 + boff);
            cp_async16(sa,      gA + koff);
            cp_async16(sa + 16, gA + koff + 8);
            cp_async16(sb,      gB + koff);
        }
        asm volatile("cp.async.commit_group;\n" ::: "memory");

        const __half* As = smh + buf * STGH64;
        const __half* Bs = As + 128 * PADH;
#pragma unroll
        for (int ks = 0; ks < 2; ks++) {
            const int kc = ks * 16;
            uint32_t af[2][4], bf[4][2];
#pragma unroll
            for (int mt = 0; mt < 2; mt++) {
                const int r = wm * 32 + mt * 16 + gid;
                af[mt][0] = *(const uint32_t*)&As[r * PADH + kc + 2 * tig];
                af[mt][1] = *(const uint32_t*)&As[(r + 8) * PADH + kc + 2 * tig];
                af[mt][2] = *(const uint32_t*)&As[r * PADH + kc + 8 + 2 * tig];
                af[mt][3] = *(const uint32_t*)&As[(r + 8) * PADH + kc + 8 + 2 * tig];
            }
#pragma unroll
            for (int nt = 0; nt < 4; nt++) {
                const int r = wn * 32 + nt * 8 + gid;
                bf[nt][0] = *(const uint32_t*)&Bs[r * PADH + kc + 2 * tig];
                bf[nt][1] = *(const uint32_t*)&Bs[r * PADH + kc + 8 + 2 * tig];
            }
#pragma unroll
            for (int mt = 0; mt < 2; mt++)
#pragma unroll
                for (int nt = 0; nt < 4; nt++)
                    mma_f16(acc[mt][nt], af[mt][0], af[mt][1], af[mt][2], af[mt][3],
                            bf[nt][0], bf[nt][1]);
        }
    }

#pragma unroll
    for (int mt = 0; mt < 2; mt++) {
        const int r0 = bm + wm * 32 + mt * 16 + gid;
#pragma unroll
        for (int nt = 0; nt < 4; nt++) {
            const int c0 = bn + wn * 32 + nt * 8 + tig * 2;
            *(float2*)&C[(size_t)r0 * N + c0]       = make_float2(acc[mt][nt][0], acc[mt][nt][1]);
            *(float2*)&C[(size_t)(r0 + 8) * N + c0] = make_float2(acc[mt][nt][2], acc[mt][nt][3]);
        }
    }
}

// ---------------------------------------------------------------------------
// FP16 tensor-core causal flash attention (R13-exact, heaviest-first).
// ---------------------------------------------------------------------------
#define KPADH 136
#define VPADH 40
#define PPADH 40
#define KTILEH (32 * KPADH)
#define VTILEH (128 * VPADH)
#define BUFH   (KTILEH + VTILEH)
#define ATTN_SMEM ((2 * BUFH + 64 * PPADH) * 2)   // 43008 bytes

__global__ __launch_bounds__(128, 2) void attn_f16_kernel(
    const __half* __restrict__ Qh, const __half* __restrict__ Kh,
    const __half* __restrict__ Vt, __half* __restrict__ Y)
{
    extern __shared__ __half smh[];
    __half* Ps = smh + 2 * BUFH;

    const int b   = blockIdx.z;
    const int h   = blockIdx.y;
    const int q0  = (int)(gridDim.x - 1 - blockIdx.x) * 64;
    const int kvh = h >> 2;
    const int tid  = threadIdx.x;
    const int warp = tid >> 5;
    const int lane = tid & 31;
    const int gid  = lane >> 2;
    const int tig  = lane & 3;

    uint32_t qf[8][4];
    {
        const __half* qp  = Qh + (size_t)(b * TSEQ + q0 + warp * 16 + gid) * CDIM + h * 128;
        const __half* qp8 = qp + 8 * CDIM;
#pragma unroll
        for (int ks = 0; ks < 8; ks++) {
            qf[ks][0] = *(const uint32_t*)&qp [ks * 16 + 2 * tig];
            qf[ks][1] = *(const uint32_t*)&qp8[ks * 16 + 2 * tig];
            qf[ks][2] = *(const uint32_t*)&qp [ks * 16 + 8 + 2 * tig];
            qf[ks][3] = *(const uint32_t*)&qp8[ks * 16 + 8 + 2 * tig];
        }
    }

    float o[16][4];
#pragma unroll
    for (int nt = 0; nt < 16; nt++)
#pragma unroll
        for (int i = 0; i < 4; i++) o[nt][i] = 0.f;
    float m0 = -1e30f, m1 = -1e30f, l0 = 0.f, l1 = 0.f;

    const int nkt = q0 / 32 + 2;

    const __half* Kbase  = Kh + (size_t)(b * TSEQ) * KVHW + kvh * 128;
    const __half* Vtbase = Vt + ((size_t)(b * NKV + kvh) * HD) * TSEQ;

    {
        __half* Kb = smh;
        __half* Vb = smh + KTILEH;
#pragma unroll
        for (int i = 0; i < 4; i++) {
            int idx = tid + i * 128;
            int kr = idx >> 4, kc = idx & 15;
            cp_async16((uint32_t)__cvta_generic_to_shared(Kb + kr * KPADH + kc * 8),
                       Kbase + (size_t)kr * KVHW + kc * 8);
            int vr = idx >> 2, vc = idx & 3;
            cp_async16((uint32_t)__cvta_generic_to_shared(Vb + vr * VPADH + vc * 8),
                       Vtbase + (size_t)vr * TSEQ + vc * 8);
        }
        asm volatile("cp.async.commit_group;\n" ::: "memory");
    }

    const int row0 = warp * 16 + gid;

    for (int t = 0; t < nkt; t++) {
        const int buf = t & 1;
        if (t + 1 < nkt) {
            const int s1 = (t + 1) * 32;
            __half* Kb = smh + (buf ^ 1) * BUFH;
            __half* Vb = Kb + KTILEH;
#pragma unroll
            for (int i = 0; i < 4; i++) {
                int idx = tid + i * 128;
                int kr = idx >> 4, kc = idx & 15;
                cp_async16((uint32_t)__cvta_generic_to_shared(Kb + kr * KPADH + kc * 8),
                           Kbase + (size_t)(s1 + kr) * KVHW + kc * 8);
                int vr = idx >> 2, vc = idx & 3;
                cp_async16((uint32_t)__cvta_generic_to_shared(Vb + vr * VPADH + vc * 8),
                           Vtbase + (size_t)vr * TSEQ + s1 + vc * 8);
            }
        }
        asm volatile("cp.async.commit_group;\n" ::: "memory");
        asm volatile("cp.async.wait_group 1;\n" ::: "memory");
        __syncthreads();

        const __half* Kb = smh + buf * BUFH;
        const __half* Vb = Kb + KTILEH;
        const int s0 = t * 32;

        float s[4][4];
#pragma unroll
        for (int nt = 0; nt < 4; nt++)
#pragma unroll
            for (int i = 0; i < 4; i++) s[nt][i] = 0.f;

#pragma unroll
        for (int ks = 0; ks < 8; ks++) {
            const int kc = ks * 16;
#pragma unroll
            for (int nt = 0; nt < 4; nt++) {
                const __half* kr = Kb + (nt * 8 + gid) * KPADH + kc + 2 * tig;
                uint32_t b0 = *(const uint32_t*)kr;
                uint32_t b1 = *(const uint32_t*)(kr + 8);
                mma_f16(s[nt], qf[ks][0], qf[ks][1], qf[ks][2], qf[ks][3], b0, b1);
            }
        }

        if (t >= nkt - 2) {
            const int r0g = q0 + row0;
#pragma unroll
            for (int nt = 0; nt < 4; nt++) {
                const int c = s0 + nt * 8 + tig * 2;
                if (c > r0g)         s[nt][0] = -1e30f;
                if (c + 1 > r0g)     s[nt][1] = -1e30f;
                if (c > r0g + 8)     s[nt][2] = -1e30f;
                if (c + 1 > r0g + 8) s[nt][3] = -1e30f;
            }
        }

        float rm0 = s[0][0], rm1 = s[0][2];
#pragma unroll
        for (int nt = 0; nt < 4; nt++) {
            rm0 = fmaxf(rm0, fmaxf(s[nt][0], s[nt][1]));
            rm1 = fmaxf(rm1, fmaxf(s[nt][2], s[nt][3]));
        }
        rm0 = fmaxf(rm0, __shfl_xor_sync(0xffffffffu, rm0, 1));
        rm0 = fmaxf(rm0, __shfl_xor_sync(0xffffffffu, rm0, 2));
        rm1 = fmaxf(rm1, __shfl_xor_sync(0xffffffffu, rm1, 1));
        rm1 = fmaxf(rm1, __shfl_xor_sync(0xffffffffu, rm1, 2));

        float mt0 = fmaxf(m0, rm0), mt1 = fmaxf(m1, rm1);
        float c0 = __expf(m0 - mt0), c1 = __expf(m1 - mt1);
        m0 = mt0; m1 = mt1;

        float rs0 = 0.f, rs1 = 0.f;
#pragma unroll
        for (int nt = 0; nt < 4; nt++) {
            s[nt][0] = __expf(s[nt][0] - m0); rs0 += s[nt][0];
            s[nt][1] = __expf(s[nt][1] - m0); rs0 += s[nt][1];
            s[nt][2] = __expf(s[nt][2] - m1); rs1 += s[nt][2];
            s[nt][3] = __expf(s[nt][3] - m1); rs1 += s[nt][3];
        }
        rs0 += __shfl_xor_sync(0xffffffffu, rs0, 1);
        rs0 += __shfl_xor_sync(0xffffffffu, rs0, 2);
        rs1 += __shfl_xor_sync(0xffffffffu, rs1, 1);
        rs1 += __shfl_xor_sync(0xffffffffu, rs1, 2);
        l0 = l0 * c0 + rs0;
        l1 = l1 * c1 + rs1;

#pragma unroll
        for (int nt = 0; nt < 16; nt++) {
            o[nt][0] *= c0; o[nt][1] *= c0;
            o[nt][2] *= c1; o[nt][3] *= c1;
        }

#pragma unroll
        for (int nt = 0; nt < 4; nt++) {
            *(__half2*)&Ps[row0 * PPADH + nt * 8 + 2 * tig]       = __floats2half2_rn(s[nt][0], s[nt][1]);
            *(__half2*)&Ps[(row0 + 8) * PPADH + nt * 8 + 2 * tig] = __floats2half2_rn(s[nt][2], s[nt][3]);
        }
        __syncwarp();

#pragma unroll
        for (int ks = 0; ks < 2; ks++) {
            const int kc = ks * 16;
            uint32_t a0 = *(const uint32_t*)&Ps[row0 * PPADH + kc + 2 * tig];
            uint32_t a1 = *(const uint32_t*)&Ps[(row0 + 8) * PPADH + kc + 2 * tig];
            uint32_t a2 = *(const uint32_t*)&Ps[row0 * PPADH + kc + 8 + 2 * tig];
            uint32_t a3 = *(const uint32_t*)&Ps[(row0 + 8) * PPADH + kc + 8 + 2 * tig];
#pragma unroll
            for (int nt = 0; nt < 16; nt++) {
                const __half* vr = Vb + (nt * 8 + gid) * VPADH + kc + 2 * tig;
                uint32_t b0 = *(const uint32_t*)vr;
                uint32_t b1 = *(const uint32_t*)(vr + 8);
                mma_f16(o[nt], a0, a1, a2, a3, b0, b1);
            }
        }
        __syncthreads();
    }

    const float inv0 = 1.f / l0, inv1 = 1.f / l1;
    __half* yp  = Y + (size_t)(b * TSEQ + q0 + row0) * CDIM + h * 128;
    __half* yp8 = yp + 8 * CDIM;
#pragma unroll
    for (int nt = 0; nt < 16; nt++) {
        const int c = nt * 8 + tig * 2;
        *(__half2*)&yp [c] = __floats2half2_rn(o[nt][0] * inv0, o[nt][1] * inv0);
        *(__half2*)&yp8[c] = __floats2half2_rn(o[nt][2] * inv1, o[nt][3] * inv1);
    }
}

// ---------------------------------------------------------------------------
extern "C" void kernel_launch(void* const* d_in, const int* in_sizes, int n_in,
                              void* d_out, int out_size)
{
    const float* x   = (const float*)d_in[0];
    const float* Wq  = (const float*)d_in[1];
    const float* Wkv = (const float*)d_in[2];
    const float* Wo  = (const float*)d_in[3];
    float* out = (float*)d_out;

    __half *pQh, *pKh, *pVth, *pYh, *pXh, *pWqh, *pWkvh, *pWoh;
    cudaGetSymbolAddress((void**)&pQh,   g_Qh);
    cudaGetSymbolAddress((void**)&pKh,   g_Kh);
    cudaGetSymbolAddress((void**)&pVth,  g_Vth);
    cudaGetSymbolAddress((void**)&pYh,   g_Yh);
    cudaGetSymbolAddress((void**)&pXh,   g_Xh);
    cudaGetSymbolAddress((void**)&pWqh,  g_Wqh);
    cudaGetSymbolAddress((void**)&pWkvh, g_Wkvh);
    cudaGetSymbolAddress((void**)&pWoh,  g_Woh);

    cudaFuncSetAttribute(gemm_qkv, cudaFuncAttributeMaxDynamicSharedMemorySize, GEMM_SMEM);
    cudaFuncSetAttribute(gemm_wo64, cudaFuncAttributeMaxDynamicSharedMemorySize, GEMM64_SMEM);
    cudaFuncSetAttribute(attn_f16_kernel, cudaFuncAttributeMaxDynamicSharedMemorySize, ATTN_SMEM);

    // 0) convert all four inputs to fp16 in one launch
    cvt_all_kernel<<<(N4_ALL + 255) / 256, 256>>>(x, Wq, Wkv, Wo, pXh, pWqh, pWkvh, pWoh);

    // 1) fused QKV projection (Q: rope+scale -> Qh; K: rope -> Kh; V: ^T -> Vth)
    gemm_qkv<<<dim3((CDIM + KVW) / 128, MROWS / 128), 256, GEMM_SMEM>>>(
        pXh, pWqh, pWkvh, pQh, pKh, pVth, CDIM);

    // 2) fp16 tensor-core causal flash attention (fp16 Y out)
    attn_f16_kernel<<<dim3(TSEQ / 64, NH, NB), 128, ATTN_SMEM>>>(pQh, pKh, pVth, pYh);

    // 3) out = Y @ Wo^T (128x64 tiles, 3 CTAs/SM)
    gemm_wo64<<<dim3(CDIM / 64, MROWS / 128), 256, GEMM64_SMEM>>>(
        pYh, pWoh, out, CDIM, CDIM);
}